// round 15
// baseline (speedup 1.0000x reference)
#include <cuda_runtime.h>
#include <cuda_fp16.h>
#include <math_constants.h>
#include <stdint.h>

#define CCH 256               // channels
#define NLEV 4

// Transposed scratch (HW, C) for all 4 pyramid levels, fp16.
__device__ __align__(16) __half g_featT[22282240];

// ---------------------------------------------------------------------------
// Transpose (C, HW) -> (HW, C), fp32 -> fp16 (round-12 proven body).
// c0base selects a channel sub-range: tile base = c0base + blockIdx.y*64.
// ---------------------------------------------------------------------------
__global__ void transpose_chw_to_hwc(const float* __restrict__ in,
                                     size_t out_off, int HW, int c0base) {
    __shared__ __half2 tile[32][33];   // [hw][channel-pair]
    const int tx = threadIdx.x;          // 0..31 -> hw within tile
    const int ty = threadIdx.y;          // 0..7
    const int x  = blockIdx.x * 32 + tx; // HW index
    const int c0 = c0base + blockIdx.y * 64;   // channel tile base

    const float* __restrict__ base = in + (size_t)c0 * HW + x;
    const size_t cstride = (size_t)HW;

    // 8 independent LDG.32, all issued before any consumption.
    const float a0 = base[(2 * (ty +  0) + 0) * cstride];
    const float b0 = base[(2 * (ty +  0) + 1) * cstride];
    const float a1 = base[(2 * (ty +  8) + 0) * cstride];
    const float b1 = base[(2 * (ty +  8) + 1) * cstride];
    const float a2 = base[(2 * (ty + 16) + 0) * cstride];
    const float b2 = base[(2 * (ty + 16) + 1) * cstride];
    const float a3 = base[(2 * (ty + 24) + 0) * cstride];
    const float b3 = base[(2 * (ty + 24) + 1) * cstride];

    tile[tx][ty +  0] = __floats2half2_rn(a0, b0);
    tile[tx][ty +  8] = __floats2half2_rn(a1, b1);
    tile[tx][ty + 16] = __floats2half2_rn(a2, b2);
    tile[tx][ty + 24] = __floats2half2_rn(a3, b3);
    __syncthreads();

    const int xo = blockIdx.x * 32;
#pragma unroll
    for (int r0 = 0; r0 < 32; r0 += 8) {
        const int r = r0 + ty;           // hw row within tile
        *reinterpret_cast<__half2*>(
            &g_featT[out_off + (size_t)(xo + r) * CCH + c0 + 2 * tx]) =
            tile[r][tx];
    }
}

// ---------------------------------------------------------------------------
// Per-sample accumulate: 4 corner uint4 (8 halves each) * half2 weights.
// ---------------------------------------------------------------------------
__device__ __forceinline__ void accum_sample(
    const uint4& ua, const uint4& ub, const uint4& uc, const uint4& ud,
    const uint4& wt, __half2 vmax2[4]) {
    const __half2 wa2 = *reinterpret_cast<const __half2*>(&wt.x);
    const __half2 wb2 = *reinterpret_cast<const __half2*>(&wt.y);
    const __half2 wc2 = *reinterpret_cast<const __half2*>(&wt.z);
    const __half2 wd2 = *reinterpret_cast<const __half2*>(&wt.w);
    const __half2* ha = reinterpret_cast<const __half2*>(&ua);
    const __half2* hb = reinterpret_cast<const __half2*>(&ub);
    const __half2* hc = reinterpret_cast<const __half2*>(&uc);
    const __half2* hd = reinterpret_cast<const __half2*>(&ud);
#pragma unroll
    for (int q = 0; q < 4; ++q) {
        __half2 acc = __hmul2(wa2, ha[q]);
        acc = __hfma2(wb2, hb[q], acc);
        acc = __hfma2(wc2, hc[q], acc);
        acc = __hfma2(wd2, hd[q], acc);
        vmax2[q] = __hmax2(vmax2[q], acc);
    }
}

// ---------------------------------------------------------------------------
// ROIAlign kernel (round-11/12 proven body; regs 77, MLP 16).
// chunk = chunk_base + blockIdx.y (64-channel chunks).
// target_lvl: 0 -> lvl==0, 1 -> lvl==1, 2 -> lvl>=2.
// ---------------------------------------------------------------------------
__global__ __launch_bounds__(128, 6) void roialign_kernel(
    const float* __restrict__ proposals,
    float* __restrict__ out,
    int target_lvl,
    int chunk_base) {

    __shared__ float sOut[64 * 49];    // 12544 B
    __shared__ uint4 s_off[196];       // corner element-offsets (a,b,c,d)
    __shared__ uint4 s_wt [196];       // 4 half2 weight splats (wa,wb,wc,wd)

    const int n     = blockIdx.x;
    const int chunk = chunk_base + (int)blockIdx.y;
    const int tid   = threadIdx.x;
    const int g     = tid & 7;        // channel group (8 channels each)
    const int p     = tid >> 3;       // pixel slice 0..15

    // --- per-proposal setup (uniform across block) ---
    const float4 box = *reinterpret_cast<const float4*>(proposals + n * 4);
    const float px1 = box.x, py1 = box.y, px2 = box.z, py2 = box.w;

    const float pw = px2 - px1;
    const float ph = py2 - py1;
    const float lf = floorf(2.0f + log2f(sqrtf(pw * ph) / 224.0f));
    int lvl = (int)lf;
    lvl = lvl < 0 ? 0 : (lvl > 3 ? 3 : lvl);

    // Level gate (uniform per block, before any __syncthreads).
    const int lvlClass = lvl >= 2 ? 2 : lvl;
    if (lvlClass != target_lvl) return;

    const float scales[NLEV] = {0.25f, 0.125f, 0.0625f, 0.03125f};
    const int   sizes [NLEV] = {256, 128, 64, 32};
    const size_t offs [NLEV] = {0, 16777216, 16777216 + 4194304,
                                16777216 + 4194304 + 1048576};

    const float sc  = scales[lvl];
    const int   Sz  = sizes[lvl];
    const float bx1 = px1 * sc, by1 = py1 * sc;
    const float bx2 = px2 * sc, by2 = py2 * sc;
    const float w_unit = ((bx2 - bx1) / 7.0f) * 0.5f;
    const float h_unit = ((by2 - by1) / 7.0f) * 0.5f;

    // --- per-sample precompute: offsets + half2-splat weights ---
    for (int s = tid; s < 196; s += 128) {
        const int gy = s / 14;
        const int gx = s - gy * 14;

        const float x  = bx1 + ((float)gx + 0.5f) * w_unit;
        const float y  = by1 + ((float)gy + 0.5f) * h_unit;
        const int   xf = (int)floorf(x);
        const int   yf = (int)floorf(y);
        int x0 = xf;     x0 = x0 < 0 ? 0 : (x0 > Sz - 1 ? Sz - 1 : x0);
        int x1 = xf + 1; x1 = x1 < 0 ? 0 : (x1 > Sz - 1 ? Sz - 1 : x1);
        int y0 = yf;     y0 = y0 < 0 ? 0 : (y0 > Sz - 1 ? Sz - 1 : y0);
        int y1 = yf + 1; y1 = y1 < 0 ? 0 : (y1 > Sz - 1 ? Sz - 1 : y1);

        const float dx0 = x - (float)x0;   // (x - x0f)
        const float dx1 = (float)x1 - x;   // (x1f - x)
        const float dy0 = y - (float)y0;   // (y - y0f)
        const float dy1 = (float)y1 - y;   // (y1f - y)

        uint4 off;
        off.x = (unsigned)((y0 * Sz + x0) * CCH);   // la
        off.y = (unsigned)((y1 * Sz + x0) * CCH);   // lb
        off.z = (unsigned)((y0 * Sz + x1) * CCH);   // lc
        off.w = (unsigned)((y1 * Sz + x1) * CCH);   // ld
        s_off[s] = off;

        const __half2 wa = __float2half2_rn(dx1 * dy1);
        const __half2 wb = __float2half2_rn(dx1 * dy0);
        const __half2 wc = __float2half2_rn(dx0 * dy1);
        const __half2 wd = __float2half2_rn(dx0 * dy0);
        uint4 wt;
        wt.x = *reinterpret_cast<const unsigned*>(&wa);
        wt.y = *reinterpret_cast<const unsigned*>(&wb);
        wt.z = *reinterpret_cast<const unsigned*>(&wc);
        wt.w = *reinterpret_cast<const unsigned*>(&wd);
        s_wt[s] = wt;
    }
    __syncthreads();

    const int cb = g * 8;                    // channel within chunk (0..56)
    const int cg = chunk * 64 + cb;          // global channel
    const __half* __restrict__ fbase = g_featT + offs[lvl] + cg;

    const __half2 neginf2 = __float2half2_rn(-CUDART_INF_F);

    for (int pix = p; pix < 49; pix += 16) {
        const int oy = pix / 7;
        const int ox = pix - oy * 7;
        const int sTL = (oy * 2) * 14 + ox * 2;

        __half2 vmax2[4];
#pragma unroll
        for (int q = 0; q < 4; ++q) vmax2[q] = neginf2;

        const int s0 = sTL, s1i = sTL + 1, s2i = sTL + 14, s3i = sTL + 15;
        const uint4 off0 = s_off[s0];
        const uint4 off1 = s_off[s1i];
        const uint4 off2 = s_off[s2i];
        const uint4 off3 = s_off[s3i];
        const uint4 wt0  = s_wt[s0];
        const uint4 wt1  = s_wt[s1i];
        const uint4 wt2  = s_wt[s2i];
        const uint4 wt3  = s_wt[s3i];

        const uint4 a0 = *reinterpret_cast<const uint4*>(fbase + off0.x);
        const uint4 b0 = *reinterpret_cast<const uint4*>(fbase + off0.y);
        const uint4 c0 = *reinterpret_cast<const uint4*>(fbase + off0.z);
        const uint4 d0 = *reinterpret_cast<const uint4*>(fbase + off0.w);
        const uint4 a1 = *reinterpret_cast<const uint4*>(fbase + off1.x);
        const uint4 b1 = *reinterpret_cast<const uint4*>(fbase + off1.y);
        const uint4 c1 = *reinterpret_cast<const uint4*>(fbase + off1.z);
        const uint4 d1 = *reinterpret_cast<const uint4*>(fbase + off1.w);
        const uint4 a2 = *reinterpret_cast<const uint4*>(fbase + off2.x);
        const uint4 b2 = *reinterpret_cast<const uint4*>(fbase + off2.y);
        const uint4 c2 = *reinterpret_cast<const uint4*>(fbase + off2.z);
        const uint4 d2 = *reinterpret_cast<const uint4*>(fbase + off2.w);
        const uint4 a3 = *reinterpret_cast<const uint4*>(fbase + off3.x);
        const uint4 b3 = *reinterpret_cast<const uint4*>(fbase + off3.y);
        const uint4 c3 = *reinterpret_cast<const uint4*>(fbase + off3.z);
        const uint4 d3 = *reinterpret_cast<const uint4*>(fbase + off3.w);

        accum_sample(a0, b0, c0, d0, wt0, vmax2);
        accum_sample(a1, b1, c1, d1, wt1, vmax2);
        accum_sample(a2, b2, c2, d2, wt2, vmax2);
        accum_sample(a3, b3, c3, d3, wt3, vmax2);

        // Stage in smem (fp32), layout (64, 49).
#pragma unroll
        for (int q = 0; q < 4; ++q) {
            const float2 f = __half22float2(vmax2[q]);
            sOut[(cb + 2 * q + 0) * 49 + pix] = f.x;
            sOut[(cb + 2 * q + 1) * 49 + pix] = f.y;
        }
    }

    __syncthreads();

    // Coalesced flush: 64*49 = 3136 floats = 784 float4.
    float4* __restrict__ o4 = reinterpret_cast<float4*>(
        out + (size_t)n * 12544 + (size_t)chunk * 3136);
    const float4* __restrict__ s4 = reinterpret_cast<const float4*>(sOut);
    for (int k = tid; k < 784; k += 128) {
        o4[k] = s4[k];
    }
}

// ---------------------------------------------------------------------------
// Launch graph — T2 split in channel halves so ROI0 overlaps T2's tail:
//   main: T2a(ch 0-127) [e2a] -> T2b(ch 128-255) -> ROI0 chunks {2,3}
//   s1:   T3 -> ROI1 (all 4 chunks)                                 [ev1]
//   s2:   T4 -> T5 -> ROI2 (all 4 chunks) -> wait e2a -> ROI0 {0,1} [ev2]
// ---------------------------------------------------------------------------
extern "C" void kernel_launch(void* const* d_in, const int* in_sizes, int n_in,
                              void* d_out, int out_size) {
    const float* p2 = (const float*)d_in[0];  // (1,256,256,256)
    const float* p3 = (const float*)d_in[1];  // (1,256,128,128)
    const float* p4 = (const float*)d_in[2];  // (1,256,64,64)
    const float* p5 = (const float*)d_in[3];  // (1,256,32,32)
    const float* proposals = (const float*)d_in[4];
    const int N = in_sizes[4] / 4;

    const size_t OFF2 = 0;
    const size_t OFF3 = 16777216;
    const size_t OFF4 = 16777216 + 4194304;
    const size_t OFF5 = 16777216 + 4194304 + 1048576;

    static cudaStream_t s1 = nullptr, s2 = nullptr;
    static cudaEvent_t evRoot = nullptr, e2a = nullptr, ev1 = nullptr,
                       ev2 = nullptr;
    if (s1 == nullptr) {
        cudaStreamCreateWithFlags(&s1, cudaStreamNonBlocking);
        cudaStreamCreateWithFlags(&s2, cudaStreamNonBlocking);
        cudaEventCreateWithFlags(&evRoot, cudaEventDisableTiming);
        cudaEventCreateWithFlags(&e2a, cudaEventDisableTiming);
        cudaEventCreateWithFlags(&ev1, cudaEventDisableTiming);
        cudaEventCreateWithFlags(&ev2, cudaEventDisableTiming);
    }

    dim3 tb(32, 8);
    float* outf = (float*)d_out;

    // Fork side streams off the main (capture) stream.
    cudaEventRecord(evRoot, 0);
    cudaStreamWaitEvent(s1, evRoot, 0);
    cudaStreamWaitEvent(s2, evRoot, 0);

    // main: T2 halves, then ROI0 chunks {2,3}.
    {
        dim3 gh(65536 / 32, 2);
        transpose_chw_to_hwc<<<gh, tb>>>(p2, OFF2, 65536, 0);    // ch 0-127
        cudaEventRecord(e2a, 0);
        transpose_chw_to_hwc<<<gh, tb>>>(p2, OFF2, 65536, 128);  // ch 128-255
        dim3 rg(N, 2);
        roialign_kernel<<<rg, 128>>>(proposals, outf, 0, 2);
    }
    // s1: T3, then ROI1 (all 4 chunks).
    {
        dim3 g3(16384 / 32, 4);
        transpose_chw_to_hwc<<<g3, tb, 0, s1>>>(p3, OFF3, 16384, 0);
        dim3 rg(N, 4);
        roialign_kernel<<<rg, 128, 0, s1>>>(proposals, outf, 1, 0);
        cudaEventRecord(ev1, s1);
    }
    // s2: T4 + T5, ROI2, then ROI0 chunks {0,1} after T2a.
    {
        dim3 g4(4096 / 32, 4);
        transpose_chw_to_hwc<<<g4, tb, 0, s2>>>(p4, OFF4, 4096, 0);
        dim3 g5(1024 / 32, 4);
        transpose_chw_to_hwc<<<g5, tb, 0, s2>>>(p5, OFF5, 1024, 0);
        dim3 rg(N, 4);
        roialign_kernel<<<rg, 128, 0, s2>>>(proposals, outf, 2, 0);
        cudaStreamWaitEvent(s2, e2a, 0);
        dim3 rh(N, 2);
        roialign_kernel<<<rh, 128, 0, s2>>>(proposals, outf, 0, 0);
        cudaEventRecord(ev2, s2);
    }

    // Join side streams back into the main stream.
    cudaStreamWaitEvent(0, ev1, 0);
    cudaStreamWaitEvent(0, ev2, 0);
}

// round 16
// speedup vs baseline: 1.0875x; 1.0875x over previous
#include <cuda_runtime.h>
#include <cuda_fp16.h>
#include <math_constants.h>
#include <stdint.h>

#define CCH 256               // channels
#define NLEV 4

// Transposed scratch (HW, C) for all 4 pyramid levels, fp16.
__device__ __align__(16) __half g_featT[22282240];

// ---------------------------------------------------------------------------
// Transpose (C, HW) -> (HW, C), fp32 -> fp16 (round-12 proven form).
// ---------------------------------------------------------------------------
__global__ void transpose_chw_to_hwc(const float* __restrict__ in,
                                     size_t out_off, int HW) {
    __shared__ __half2 tile[32][33];   // [hw][channel-pair]
    const int tx = threadIdx.x;          // 0..31 -> hw within tile
    const int ty = threadIdx.y;          // 0..7
    const int x  = blockIdx.x * 32 + tx; // HW index
    const int c0 = blockIdx.y * 64;      // channel tile base (64 channels)

    const float* __restrict__ base = in + (size_t)c0 * HW + x;
    const size_t cstride = (size_t)HW;

    // 8 independent LDG.32, all issued before any consumption.
    const float a0 = base[(2 * (ty +  0) + 0) * cstride];
    const float b0 = base[(2 * (ty +  0) + 1) * cstride];
    const float a1 = base[(2 * (ty +  8) + 0) * cstride];
    const float b1 = base[(2 * (ty +  8) + 1) * cstride];
    const float a2 = base[(2 * (ty + 16) + 0) * cstride];
    const float b2 = base[(2 * (ty + 16) + 1) * cstride];
    const float a3 = base[(2 * (ty + 24) + 0) * cstride];
    const float b3 = base[(2 * (ty + 24) + 1) * cstride];

    tile[tx][ty +  0] = __floats2half2_rn(a0, b0);
    tile[tx][ty +  8] = __floats2half2_rn(a1, b1);
    tile[tx][ty + 16] = __floats2half2_rn(a2, b2);
    tile[tx][ty + 24] = __floats2half2_rn(a3, b3);
    __syncthreads();

    const int xo = blockIdx.x * 32;
#pragma unroll
    for (int r0 = 0; r0 < 32; r0 += 8) {
        const int r = r0 + ty;           // hw row within tile
        *reinterpret_cast<__half2*>(
            &g_featT[out_off + (size_t)(xo + r) * CCH + c0 + 2 * tx]) =
            tile[r][tx];
    }
}

// ---------------------------------------------------------------------------
// Per-sample accumulate: 4 corner uint4 (8 halves each) * half2 weights.
// ---------------------------------------------------------------------------
__device__ __forceinline__ void accum_sample(
    const uint4& ua, const uint4& ub, const uint4& uc, const uint4& ud,
    const uint4& wt, __half2 vmax2[4]) {
    const __half2 wa2 = *reinterpret_cast<const __half2*>(&wt.x);
    const __half2 wb2 = *reinterpret_cast<const __half2*>(&wt.y);
    const __half2 wc2 = *reinterpret_cast<const __half2*>(&wt.z);
    const __half2 wd2 = *reinterpret_cast<const __half2*>(&wt.w);
    const __half2* ha = reinterpret_cast<const __half2*>(&ua);
    const __half2* hb = reinterpret_cast<const __half2*>(&ub);
    const __half2* hc = reinterpret_cast<const __half2*>(&uc);
    const __half2* hd = reinterpret_cast<const __half2*>(&ud);
#pragma unroll
    for (int q = 0; q < 4; ++q) {
        __half2 acc = __hmul2(wa2, ha[q]);
        acc = __hfma2(wb2, hb[q], acc);
        acc = __hfma2(wc2, hc[q], acc);
        acc = __hfma2(wd2, hd[q], acc);
        vmax2[q] = __hmax2(vmax2[q], acc);
    }
}

// ---------------------------------------------------------------------------
// ROIAlign kernel (round-11/12 proven body; regs 77, MLP 16).
// Grid (N, 4). Gate: target_lvl == 1 -> handle lvl-class 1 only;
// target_lvl == 3 -> handle lvl-classes {0, 2} (combined tail launch).
// ---------------------------------------------------------------------------
__global__ __launch_bounds__(128, 6) void roialign_kernel(
    const float* __restrict__ proposals,
    float* __restrict__ out,
    int target_lvl) {

    __shared__ float sOut[64 * 49];    // 12544 B
    __shared__ uint4 s_off[196];       // corner element-offsets (a,b,c,d)
    __shared__ uint4 s_wt [196];       // 4 half2 weight splats (wa,wb,wc,wd)

    const int n     = blockIdx.x;
    const int chunk = blockIdx.y;     // 0..3 -> channels chunk*64 .. +63
    const int tid   = threadIdx.x;
    const int g     = tid & 7;        // channel group (8 channels each)
    const int p     = tid >> 3;       // pixel slice 0..15

    // --- per-proposal setup (uniform across block) ---
    const float4 box = *reinterpret_cast<const float4*>(proposals + n * 4);
    const float px1 = box.x, py1 = box.y, px2 = box.z, py2 = box.w;

    const float pw = px2 - px1;
    const float ph = py2 - py1;
    const float lf = floorf(2.0f + log2f(sqrtf(pw * ph) / 224.0f));
    int lvl = (int)lf;
    lvl = lvl < 0 ? 0 : (lvl > 3 ? 3 : lvl);

    // Level gate (uniform per block, before any __syncthreads).
    const int lvlClass = lvl >= 2 ? 2 : lvl;
    const bool run = (target_lvl == 3) ? (lvlClass != 1)
                                       : (lvlClass == target_lvl);
    if (!run) return;

    const float scales[NLEV] = {0.25f, 0.125f, 0.0625f, 0.03125f};
    const int   sizes [NLEV] = {256, 128, 64, 32};
    const size_t offs [NLEV] = {0, 16777216, 16777216 + 4194304,
                                16777216 + 4194304 + 1048576};

    const float sc  = scales[lvl];
    const int   Sz  = sizes[lvl];
    const float bx1 = px1 * sc, by1 = py1 * sc;
    const float bx2 = px2 * sc, by2 = py2 * sc;
    const float w_unit = ((bx2 - bx1) / 7.0f) * 0.5f;
    const float h_unit = ((by2 - by1) / 7.0f) * 0.5f;

    // --- per-sample precompute: offsets + half2-splat weights ---
    for (int s = tid; s < 196; s += 128) {
        const int gy = s / 14;
        const int gx = s - gy * 14;

        const float x  = bx1 + ((float)gx + 0.5f) * w_unit;
        const float y  = by1 + ((float)gy + 0.5f) * h_unit;
        const int   xf = (int)floorf(x);
        const int   yf = (int)floorf(y);
        int x0 = xf;     x0 = x0 < 0 ? 0 : (x0 > Sz - 1 ? Sz - 1 : x0);
        int x1 = xf + 1; x1 = x1 < 0 ? 0 : (x1 > Sz - 1 ? Sz - 1 : x1);
        int y0 = yf;     y0 = y0 < 0 ? 0 : (y0 > Sz - 1 ? Sz - 1 : y0);
        int y1 = yf + 1; y1 = y1 < 0 ? 0 : (y1 > Sz - 1 ? Sz - 1 : y1);

        const float dx0 = x - (float)x0;   // (x - x0f)
        const float dx1 = (float)x1 - x;   // (x1f - x)
        const float dy0 = y - (float)y0;   // (y - y0f)
        const float dy1 = (float)y1 - y;   // (y1f - y)

        uint4 off;
        off.x = (unsigned)((y0 * Sz + x0) * CCH);   // la
        off.y = (unsigned)((y1 * Sz + x0) * CCH);   // lb
        off.z = (unsigned)((y0 * Sz + x1) * CCH);   // lc
        off.w = (unsigned)((y1 * Sz + x1) * CCH);   // ld
        s_off[s] = off;

        const __half2 wa = __float2half2_rn(dx1 * dy1);
        const __half2 wb = __float2half2_rn(dx1 * dy0);
        const __half2 wc = __float2half2_rn(dx0 * dy1);
        const __half2 wd = __float2half2_rn(dx0 * dy0);
        uint4 wt;
        wt.x = *reinterpret_cast<const unsigned*>(&wa);
        wt.y = *reinterpret_cast<const unsigned*>(&wb);
        wt.z = *reinterpret_cast<const unsigned*>(&wc);
        wt.w = *reinterpret_cast<const unsigned*>(&wd);
        s_wt[s] = wt;
    }
    __syncthreads();

    const int cb = g * 8;                    // channel within chunk (0..56)
    const int cg = chunk * 64 + cb;          // global channel
    const __half* __restrict__ fbase = g_featT + offs[lvl] + cg;

    const __half2 neginf2 = __float2half2_rn(-CUDART_INF_F);

    for (int pix = p; pix < 49; pix += 16) {
        const int oy = pix / 7;
        const int ox = pix - oy * 7;
        const int sTL = (oy * 2) * 14 + ox * 2;

        __half2 vmax2[4];
#pragma unroll
        for (int q = 0; q < 4; ++q) vmax2[q] = neginf2;

        const int s0 = sTL, s1i = sTL + 1, s2i = sTL + 14, s3i = sTL + 15;
        const uint4 off0 = s_off[s0];
        const uint4 off1 = s_off[s1i];
        const uint4 off2 = s_off[s2i];
        const uint4 off3 = s_off[s3i];
        const uint4 wt0  = s_wt[s0];
        const uint4 wt1  = s_wt[s1i];
        const uint4 wt2  = s_wt[s2i];
        const uint4 wt3  = s_wt[s3i];

        const uint4 a0 = *reinterpret_cast<const uint4*>(fbase + off0.x);
        const uint4 b0 = *reinterpret_cast<const uint4*>(fbase + off0.y);
        const uint4 c0 = *reinterpret_cast<const uint4*>(fbase + off0.z);
        const uint4 d0 = *reinterpret_cast<const uint4*>(fbase + off0.w);
        const uint4 a1 = *reinterpret_cast<const uint4*>(fbase + off1.x);
        const uint4 b1 = *reinterpret_cast<const uint4*>(fbase + off1.y);
        const uint4 c1 = *reinterpret_cast<const uint4*>(fbase + off1.z);
        const uint4 d1 = *reinterpret_cast<const uint4*>(fbase + off1.w);
        const uint4 a2 = *reinterpret_cast<const uint4*>(fbase + off2.x);
        const uint4 b2 = *reinterpret_cast<const uint4*>(fbase + off2.y);
        const uint4 c2 = *reinterpret_cast<const uint4*>(fbase + off2.z);
        const uint4 d2 = *reinterpret_cast<const uint4*>(fbase + off2.w);
        const uint4 a3 = *reinterpret_cast<const uint4*>(fbase + off3.x);
        const uint4 b3 = *reinterpret_cast<const uint4*>(fbase + off3.y);
        const uint4 c3 = *reinterpret_cast<const uint4*>(fbase + off3.z);
        const uint4 d3 = *reinterpret_cast<const uint4*>(fbase + off3.w);

        accum_sample(a0, b0, c0, d0, wt0, vmax2);
        accum_sample(a1, b1, c1, d1, wt1, vmax2);
        accum_sample(a2, b2, c2, d2, wt2, vmax2);
        accum_sample(a3, b3, c3, d3, wt3, vmax2);

        // Stage in smem (fp32), layout (64, 49).
#pragma unroll
        for (int q = 0; q < 4; ++q) {
            const float2 f = __half22float2(vmax2[q]);
            sOut[(cb + 2 * q + 0) * 49 + pix] = f.x;
            sOut[(cb + 2 * q + 1) * 49 + pix] = f.y;
        }
    }

    __syncthreads();

    // Coalesced flush: 64*49 = 3136 floats = 784 float4.
    float4* __restrict__ o4 = reinterpret_cast<float4*>(
        out + (size_t)n * 12544 + (size_t)chunk * 3136);
    const float4* __restrict__ s4 = reinterpret_cast<const float4*>(sOut);
    for (int k = tid; k < 784; k += 128) {
        o4[k] = s4[k];
    }
}

// ---------------------------------------------------------------------------
// Launch graph — ROI0 and ROI2 merged into one wide tail launch:
//   s1:   T(p3) -> ROI(lvl==1)                       [ev1]
//   s2:   T(p4) -> T(p5)                             [e2]
//   main: T(p2) -> wait e2 -> ROI(lvl!=1, combined)
// 6 kernels, 2 side streams, 3 events.
// ---------------------------------------------------------------------------
extern "C" void kernel_launch(void* const* d_in, const int* in_sizes, int n_in,
                              void* d_out, int out_size) {
    const float* p2 = (const float*)d_in[0];  // (1,256,256,256)
    const float* p3 = (const float*)d_in[1];  // (1,256,128,128)
    const float* p4 = (const float*)d_in[2];  // (1,256,64,64)
    const float* p5 = (const float*)d_in[3];  // (1,256,32,32)
    const float* proposals = (const float*)d_in[4];
    const int N = in_sizes[4] / 4;

    const int    HWs [NLEV] = {65536, 16384, 4096, 1024};
    const size_t offs[NLEV] = {0, 16777216, 16777216 + 4194304,
                               16777216 + 4194304 + 1048576};

    static cudaStream_t s1 = nullptr, s2 = nullptr;
    static cudaEvent_t evRoot = nullptr, ev1 = nullptr, e2 = nullptr;
    if (s1 == nullptr) {
        cudaStreamCreateWithFlags(&s1, cudaStreamNonBlocking);
        cudaStreamCreateWithFlags(&s2, cudaStreamNonBlocking);
        cudaEventCreateWithFlags(&evRoot, cudaEventDisableTiming);
        cudaEventCreateWithFlags(&ev1, cudaEventDisableTiming);
        cudaEventCreateWithFlags(&e2, cudaEventDisableTiming);
    }

    dim3 tb(32, 8);
    dim3 rg(N, 4);
    float* outf = (float*)d_out;

    // Fork side streams off the main (capture) stream.
    cudaEventRecord(evRoot, 0);
    cudaStreamWaitEvent(s1, evRoot, 0);
    cudaStreamWaitEvent(s2, evRoot, 0);

    // s1: p3 transpose, then lvl1 ROI.
    {
        dim3 g3(HWs[1] / 32, CCH / 64);
        transpose_chw_to_hwc<<<g3, tb, 0, s1>>>(p3, offs[1], HWs[1]);
        roialign_kernel<<<rg, 128, 0, s1>>>(proposals, outf, 1);
        cudaEventRecord(ev1, s1);
    }
    // s2: p4 + p5 transposes (finish long before T2).
    {
        dim3 g4(HWs[2] / 32, CCH / 64);
        transpose_chw_to_hwc<<<g4, tb, 0, s2>>>(p4, offs[2], HWs[2]);
        dim3 g5(HWs[3] / 32, CCH / 64);
        transpose_chw_to_hwc<<<g5, tb, 0, s2>>>(p5, offs[3], HWs[3]);
        cudaEventRecord(e2, s2);
    }
    // main: p2 transpose, then combined lvl{0,2} ROI (needs T2 + T4/T5).
    {
        dim3 g2(HWs[0] / 32, CCH / 64);
        transpose_chw_to_hwc<<<g2, tb>>>(p2, offs[0], HWs[0]);
        cudaStreamWaitEvent(0, e2, 0);
        roialign_kernel<<<rg, 128>>>(proposals, outf, 3);
    }

    // Join s1 back into the main stream.
    cudaStreamWaitEvent(0, ev1, 0);
}

// round 17
// speedup vs baseline: 1.2190x; 1.1209x over previous
#include <cuda_runtime.h>
#include <cuda_fp16.h>
#include <math_constants.h>
#include <stdint.h>

#define CCH 256               // channels
#define NLEV 4

// Transposed scratch (HW, C) for all 4 pyramid levels, fp16.
__device__ __align__(16) __half g_featT[22282240];

// ---------------------------------------------------------------------------
// Transpose (C, HW) -> (HW, C), fp32 -> fp16 (round-12 proven form).
// Input reads use __ldcs (evict-streaming): the fp32 features are read once
// and must NOT evict the fp16 scratch (which ROI re-reads) from L2.
// ---------------------------------------------------------------------------
__global__ void transpose_chw_to_hwc(const float* __restrict__ in,
                                     size_t out_off, int HW) {
    __shared__ __half2 tile[32][33];   // [hw][channel-pair]
    const int tx = threadIdx.x;          // 0..31 -> hw within tile
    const int ty = threadIdx.y;          // 0..7
    const int x  = blockIdx.x * 32 + tx; // HW index
    const int c0 = blockIdx.y * 64;      // channel tile base (64 channels)

    const float* __restrict__ base = in + (size_t)c0 * HW + x;
    const size_t cstride = (size_t)HW;

    // 8 independent streaming LDG.32, all issued before any consumption.
    const float a0 = __ldcs(base + (2 * (ty +  0) + 0) * cstride);
    const float b0 = __ldcs(base + (2 * (ty +  0) + 1) * cstride);
    const float a1 = __ldcs(base + (2 * (ty +  8) + 0) * cstride);
    const float b1 = __ldcs(base + (2 * (ty +  8) + 1) * cstride);
    const float a2 = __ldcs(base + (2 * (ty + 16) + 0) * cstride);
    const float b2 = __ldcs(base + (2 * (ty + 16) + 1) * cstride);
    const float a3 = __ldcs(base + (2 * (ty + 24) + 0) * cstride);
    const float b3 = __ldcs(base + (2 * (ty + 24) + 1) * cstride);

    tile[tx][ty +  0] = __floats2half2_rn(a0, b0);
    tile[tx][ty +  8] = __floats2half2_rn(a1, b1);
    tile[tx][ty + 16] = __floats2half2_rn(a2, b2);
    tile[tx][ty + 24] = __floats2half2_rn(a3, b3);
    __syncthreads();

    const int xo = blockIdx.x * 32;
#pragma unroll
    for (int r0 = 0; r0 < 32; r0 += 8) {
        const int r = r0 + ty;           // hw row within tile
        *reinterpret_cast<__half2*>(
            &g_featT[out_off + (size_t)(xo + r) * CCH + c0 + 2 * tx]) =
            tile[r][tx];
    }
}

// ---------------------------------------------------------------------------
// Per-sample accumulate: 4 corner uint4 (8 halves each) * half2 weights.
// ---------------------------------------------------------------------------
__device__ __forceinline__ void accum_sample(
    const uint4& ua, const uint4& ub, const uint4& uc, const uint4& ud,
    const uint4& wt, __half2 vmax2[4]) {
    const __half2 wa2 = *reinterpret_cast<const __half2*>(&wt.x);
    const __half2 wb2 = *reinterpret_cast<const __half2*>(&wt.y);
    const __half2 wc2 = *reinterpret_cast<const __half2*>(&wt.z);
    const __half2 wd2 = *reinterpret_cast<const __half2*>(&wt.w);
    const __half2* ha = reinterpret_cast<const __half2*>(&ua);
    const __half2* hb = reinterpret_cast<const __half2*>(&ub);
    const __half2* hc = reinterpret_cast<const __half2*>(&uc);
    const __half2* hd = reinterpret_cast<const __half2*>(&ud);
#pragma unroll
    for (int q = 0; q < 4; ++q) {
        __half2 acc = __hmul2(wa2, ha[q]);
        acc = __hfma2(wb2, hb[q], acc);
        acc = __hfma2(wc2, hc[q], acc);
        acc = __hfma2(wd2, hd[q], acc);
        vmax2[q] = __hmax2(vmax2[q], acc);
    }
}

// ---------------------------------------------------------------------------
// ROIAlign kernel (round-11/12 proven body; regs 77, MLP 16).
// Output flush uses __stcs (streaming) — output is never re-read.
// Grid (N, 4). target_lvl: 0 -> lvl==0, 1 -> lvl==1, 2 -> lvl>=2.
// ---------------------------------------------------------------------------
__global__ __launch_bounds__(128, 6) void roialign_kernel(
    const float* __restrict__ proposals,
    float* __restrict__ out,
    int target_lvl) {

    __shared__ float sOut[64 * 49];    // 12544 B
    __shared__ uint4 s_off[196];       // corner element-offsets (a,b,c,d)
    __shared__ uint4 s_wt [196];       // 4 half2 weight splats (wa,wb,wc,wd)

    const int n     = blockIdx.x;
    const int chunk = blockIdx.y;     // 0..3 -> channels chunk*64 .. +63
    const int tid   = threadIdx.x;
    const int g     = tid & 7;        // channel group (8 channels each)
    const int p     = tid >> 3;       // pixel slice 0..15

    // --- per-proposal setup (uniform across block) ---
    const float4 box = *reinterpret_cast<const float4*>(proposals + n * 4);
    const float px1 = box.x, py1 = box.y, px2 = box.z, py2 = box.w;

    const float pw = px2 - px1;
    const float ph = py2 - py1;
    const float lf = floorf(2.0f + log2f(sqrtf(pw * ph) / 224.0f));
    int lvl = (int)lf;
    lvl = lvl < 0 ? 0 : (lvl > 3 ? 3 : lvl);

    // Level gate (uniform per block, before any __syncthreads).
    const int lvlClass = lvl >= 2 ? 2 : lvl;
    if (lvlClass != target_lvl) return;

    const float scales[NLEV] = {0.25f, 0.125f, 0.0625f, 0.03125f};
    const int   sizes [NLEV] = {256, 128, 64, 32};
    const size_t offs [NLEV] = {0, 16777216, 16777216 + 4194304,
                                16777216 + 4194304 + 1048576};

    const float sc  = scales[lvl];
    const int   Sz  = sizes[lvl];
    const float bx1 = px1 * sc, by1 = py1 * sc;
    const float bx2 = px2 * sc, by2 = py2 * sc;
    const float w_unit = ((bx2 - bx1) / 7.0f) * 0.5f;
    const float h_unit = ((by2 - by1) / 7.0f) * 0.5f;

    // --- per-sample precompute: offsets + half2-splat weights ---
    for (int s = tid; s < 196; s += 128) {
        const int gy = s / 14;
        const int gx = s - gy * 14;

        const float x  = bx1 + ((float)gx + 0.5f) * w_unit;
        const float y  = by1 + ((float)gy + 0.5f) * h_unit;
        const int   xf = (int)floorf(x);
        const int   yf = (int)floorf(y);
        int x0 = xf;     x0 = x0 < 0 ? 0 : (x0 > Sz - 1 ? Sz - 1 : x0);
        int x1 = xf + 1; x1 = x1 < 0 ? 0 : (x1 > Sz - 1 ? Sz - 1 : x1);
        int y0 = yf;     y0 = y0 < 0 ? 0 : (y0 > Sz - 1 ? Sz - 1 : y0);
        int y1 = yf + 1; y1 = y1 < 0 ? 0 : (y1 > Sz - 1 ? Sz - 1 : y1);

        const float dx0 = x - (float)x0;   // (x - x0f)
        const float dx1 = (float)x1 - x;   // (x1f - x)
        const float dy0 = y - (float)y0;   // (y - y0f)
        const float dy1 = (float)y1 - y;   // (y1f - y)

        uint4 off;
        off.x = (unsigned)((y0 * Sz + x0) * CCH);   // la
        off.y = (unsigned)((y1 * Sz + x0) * CCH);   // lb
        off.z = (unsigned)((y0 * Sz + x1) * CCH);   // lc
        off.w = (unsigned)((y1 * Sz + x1) * CCH);   // ld
        s_off[s] = off;

        const __half2 wa = __float2half2_rn(dx1 * dy1);
        const __half2 wb = __float2half2_rn(dx1 * dy0);
        const __half2 wc = __float2half2_rn(dx0 * dy1);
        const __half2 wd = __float2half2_rn(dx0 * dy0);
        uint4 wt;
        wt.x = *reinterpret_cast<const unsigned*>(&wa);
        wt.y = *reinterpret_cast<const unsigned*>(&wb);
        wt.z = *reinterpret_cast<const unsigned*>(&wc);
        wt.w = *reinterpret_cast<const unsigned*>(&wd);
        s_wt[s] = wt;
    }
    __syncthreads();

    const int cb = g * 8;                    // channel within chunk (0..56)
    const int cg = chunk * 64 + cb;          // global channel
    const __half* __restrict__ fbase = g_featT + offs[lvl] + cg;

    const __half2 neginf2 = __float2half2_rn(-CUDART_INF_F);

    for (int pix = p; pix < 49; pix += 16) {
        const int oy = pix / 7;
        const int ox = pix - oy * 7;
        const int sTL = (oy * 2) * 14 + ox * 2;

        __half2 vmax2[4];
#pragma unroll
        for (int q = 0; q < 4; ++q) vmax2[q] = neginf2;

        const int s0 = sTL, s1i = sTL + 1, s2i = sTL + 14, s3i = sTL + 15;
        const uint4 off0 = s_off[s0];
        const uint4 off1 = s_off[s1i];
        const uint4 off2 = s_off[s2i];
        const uint4 off3 = s_off[s3i];
        const uint4 wt0  = s_wt[s0];
        const uint4 wt1  = s_wt[s1i];
        const uint4 wt2  = s_wt[s2i];
        const uint4 wt3  = s_wt[s3i];

        // All 16 corner loads as individually named scalars (proven MLP-16).
        const uint4 a0 = *reinterpret_cast<const uint4*>(fbase + off0.x);
        const uint4 b0 = *reinterpret_cast<const uint4*>(fbase + off0.y);
        const uint4 c0 = *reinterpret_cast<const uint4*>(fbase + off0.z);
        const uint4 d0 = *reinterpret_cast<const uint4*>(fbase + off0.w);
        const uint4 a1 = *reinterpret_cast<const uint4*>(fbase + off1.x);
        const uint4 b1 = *reinterpret_cast<const uint4*>(fbase + off1.y);
        const uint4 c1 = *reinterpret_cast<const uint4*>(fbase + off1.z);
        const uint4 d1 = *reinterpret_cast<const uint4*>(fbase + off1.w);
        const uint4 a2 = *reinterpret_cast<const uint4*>(fbase + off2.x);
        const uint4 b2 = *reinterpret_cast<const uint4*>(fbase + off2.y);
        const uint4 c2 = *reinterpret_cast<const uint4*>(fbase + off2.z);
        const uint4 d2 = *reinterpret_cast<const uint4*>(fbase + off2.w);
        const uint4 a3 = *reinterpret_cast<const uint4*>(fbase + off3.x);
        const uint4 b3 = *reinterpret_cast<const uint4*>(fbase + off3.y);
        const uint4 c3 = *reinterpret_cast<const uint4*>(fbase + off3.z);
        const uint4 d3 = *reinterpret_cast<const uint4*>(fbase + off3.w);

        accum_sample(a0, b0, c0, d0, wt0, vmax2);
        accum_sample(a1, b1, c1, d1, wt1, vmax2);
        accum_sample(a2, b2, c2, d2, wt2, vmax2);
        accum_sample(a3, b3, c3, d3, wt3, vmax2);

        // Stage in smem (fp32), layout (64, 49).
#pragma unroll
        for (int q = 0; q < 4; ++q) {
            const float2 f = __half22float2(vmax2[q]);
            sOut[(cb + 2 * q + 0) * 49 + pix] = f.x;
            sOut[(cb + 2 * q + 1) * 49 + pix] = f.y;
        }
    }

    __syncthreads();

    // Coalesced streaming flush: 64*49 = 3136 floats = 784 float4.
    // Output is never re-read -> __stcs keeps it out of L2 residency.
    float4* __restrict__ o4 = reinterpret_cast<float4*>(
        out + (size_t)n * 12544 + (size_t)chunk * 3136);
    const float4* __restrict__ s4 = reinterpret_cast<const float4*>(sOut);
    for (int k = tid; k < 784; k += 128) {
        __stcs(o4 + k, s4[k]);
    }
}

// ---------------------------------------------------------------------------
// Launch graph (round-12 proven):
//   main: T(p2) -> ROI(lvl0)
//   s1:   T(p3) -> ROI(lvl1)
//   s2:   T(p4) -> T(p5) -> ROI(lvl>=2)
// ---------------------------------------------------------------------------
extern "C" void kernel_launch(void* const* d_in, const int* in_sizes, int n_in,
                              void* d_out, int out_size) {
    const float* p2 = (const float*)d_in[0];  // (1,256,256,256)
    const float* p3 = (const float*)d_in[1];  // (1,256,128,128)
    const float* p4 = (const float*)d_in[2];  // (1,256,64,64)
    const float* p5 = (const float*)d_in[3];  // (1,256,32,32)
    const float* proposals = (const float*)d_in[4];
    const int N = in_sizes[4] / 4;

    const int    HWs [NLEV] = {65536, 16384, 4096, 1024};
    const size_t offs[NLEV] = {0, 16777216, 16777216 + 4194304,
                               16777216 + 4194304 + 1048576};

    static cudaStream_t s1 = nullptr, s2 = nullptr;
    static cudaEvent_t evRoot = nullptr, ev1 = nullptr, ev2 = nullptr;
    if (s1 == nullptr) {
        cudaStreamCreateWithFlags(&s1, cudaStreamNonBlocking);
        cudaStreamCreateWithFlags(&s2, cudaStreamNonBlocking);
        cudaEventCreateWithFlags(&evRoot, cudaEventDisableTiming);
        cudaEventCreateWithFlags(&ev1, cudaEventDisableTiming);
        cudaEventCreateWithFlags(&ev2, cudaEventDisableTiming);
    }

    dim3 tb(32, 8);
    dim3 rg(N, 4);
    float* outf = (float*)d_out;

    // Fork side streams off the main (capture) stream.
    cudaEventRecord(evRoot, 0);
    cudaStreamWaitEvent(s1, evRoot, 0);
    cudaStreamWaitEvent(s2, evRoot, 0);

    // main: p2 transpose, then lvl0 ROI.
    {
        dim3 grid(HWs[0] / 32, CCH / 64);
        transpose_chw_to_hwc<<<grid, tb>>>(p2, offs[0], HWs[0]);
        roialign_kernel<<<rg, 128>>>(proposals, outf, 0);
    }
    // s1: p3 transpose, then lvl1 ROI.
    {
        dim3 grid(HWs[1] / 32, CCH / 64);
        transpose_chw_to_hwc<<<grid, tb, 0, s1>>>(p3, offs[1], HWs[1]);
        roialign_kernel<<<rg, 128, 0, s1>>>(proposals, outf, 1);
    }
    // s2: p4 + p5 transposes, then lvl>=2 ROI.
    {
        dim3 g4(HWs[2] / 32, CCH / 64);
        transpose_chw_to_hwc<<<g4, tb, 0, s2>>>(p4, offs[2], HWs[2]);
        dim3 g5(HWs[3] / 32, CCH / 64);
        transpose_chw_to_hwc<<<g5, tb, 0, s2>>>(p5, offs[3], HWs[3]);
        roialign_kernel<<<rg, 128, 0, s2>>>(proposals, outf, 2);
    }

    // Join side streams back into the main stream.
    cudaEventRecord(ev1, s1);
    cudaEventRecord(ev2, s2);
    cudaStreamWaitEvent(0, ev1, 0);
    cudaStreamWaitEvent(0, ev2, 0);
}